// round 2
// baseline (speedup 1.0000x reference)
#include <cuda_runtime.h>
#include <cuda_bf16.h>

#define Bsz 1024
#define Gdim 2048
#define Edim 256
#define Hdim 32
#define Vdim 14463
#define Tdim 18
#define Sdim 18      // steps actually needed (last step's output is dropped)
#define G4  128      // 4*H

// ---- scratch (no cudaMalloc allowed) ----
__device__ float g_init[Bsz * Edim];              // 1 MB   : graph projection
__device__ float g_gx0[Bsz * Sdim * G4];          // 9.4 MB : L0 input-gates precompute
__device__ float g_h2[Bsz * Sdim * Hdim];         // 2.4 MB : layer-1 hidden states

// ---- packed f32x2 helpers (Blackwell: fma.rn.f32x2 doubles fp32 FMA rate) ----
static __device__ __forceinline__ unsigned long long pk2(float lo, float hi) {
    unsigned long long r;
    asm("mov.b64 %0, {%1,%2};" : "=l"(r) : "f"(lo), "f"(hi));
    return r;
}
static __device__ __forceinline__ unsigned long long fma2(unsigned long long a,
                                                          unsigned long long b,
                                                          unsigned long long c) {
    unsigned long long d;
    asm("fma.rn.f32x2 %0, %1, %2, %3;" : "=l"(d) : "l"(a), "l"(b), "l"(c));
    return d;
}
static __device__ __forceinline__ float2 up2(unsigned long long v) {
    float2 f;
    asm("mov.b64 {%0,%1}, %2;" : "=f"(f.x), "=f"(f.y) : "l"(v));
    return f;
}

static __device__ __forceinline__ float sigf(float x) {
    return 1.0f / (1.0f + __expf(-x));
}

// ============================================================
// K0: init g_init with broadcast bias (split-K GEMM accumulates into it)
// ============================================================
__global__ void k_initbias(const float* __restrict__ b_g2e) {
    int i = blockIdx.x * blockDim.x + threadIdx.x;
    if (i < Bsz * Edim) g_init[i] = b_g2e[i & (Edim - 1)];
}

// ============================================================
// K1: g_init += graph_embedding[1024,2048] @ W_g2e[256,2048]^T   (split-K=8)
// ============================================================
__global__ __launch_bounds__(256) void k_proj(const float* __restrict__ A,
                                              const float* __restrict__ W) {
    __shared__ __align__(16) float As[32][64];   // [k][m]
    __shared__ __align__(16) float Bs[32][64];   // [k][n]
    const int tid = threadIdx.x;
    const int m0 = blockIdx.y * 64;
    const int n0 = blockIdx.x * 64;
    const int kbase = blockIdx.z * 256;

    const int tx = tid & 15, ty = tid >> 4;
    const int r = tid & 63, h = tid >> 6;            // loader row / seg-half

    const float* Ap = A + (size_t)(m0 + r) * Gdim + kbase;
    const float* Wp = W + (size_t)(n0 + r) * Gdim + kbase;

    unsigned long long acc[4][2];
#pragma unroll
    for (int j = 0; j < 4; j++) { acc[j][0] = 0ull; acc[j][1] = 0ull; }

    for (int kc = 0; kc < 256; kc += 32) {
#pragma unroll
        for (int i = 0; i < 2; i++) {
            int seg = h + i * 4;
            float4 va = *(const float4*)(Ap + kc + seg * 4);
            As[seg * 4 + 0][r] = va.x; As[seg * 4 + 1][r] = va.y;
            As[seg * 4 + 2][r] = va.z; As[seg * 4 + 3][r] = va.w;
            float4 vb = *(const float4*)(Wp + kc + seg * 4);
            Bs[seg * 4 + 0][r] = vb.x; Bs[seg * 4 + 1][r] = vb.y;
            Bs[seg * 4 + 2][r] = vb.z; Bs[seg * 4 + 3][r] = vb.w;
        }
        __syncthreads();
#pragma unroll 8
        for (int k = 0; k < 32; k++) {
            ulonglong2 a = *(const ulonglong2*)&As[k][ty * 4];
#pragma unroll
            for (int j = 0; j < 4; j++) {
                float bv = Bs[k][tx + j * 16];
                unsigned long long bd = pk2(bv, bv);
                acc[j][0] = fma2(a.x, bd, acc[j][0]);
                acc[j][1] = fma2(a.y, bd, acc[j][1]);
            }
        }
        __syncthreads();
    }
#pragma unroll
    for (int j = 0; j < 4; j++) {
        int n = n0 + tx + j * 16;
#pragma unroll
        for (int p = 0; p < 2; p++) {
            float2 v = up2(acc[j][p]);
            int m = m0 + ty * 4 + p * 2;
            atomicAdd(&g_init[m * Edim + n], v.x);
            atomicAdd(&g_init[(m + 1) * Edim + n], v.y);
        }
    }
}

// ============================================================
// K2: g_gx0[m,128] = x_m @ W_ih0^T + (b_ih0+b_hh0),
//     x_m gathered: s==0 -> g_init row, else emb_table[sentence[b][s-1]]
//     M=18432 (64/block), N=128, K=256
// ============================================================
__global__ __launch_bounds__(256) void k_gx(const int* __restrict__ sent,
                                            const float* __restrict__ emb,
                                            const float* __restrict__ Wih0,
                                            const float* __restrict__ bih0,
                                            const float* __restrict__ bhh0) {
    __shared__ __align__(16) float As[32][64];    // [k][m]
    __shared__ __align__(16) float Bs[32][128];   // [k][n]
    const int tid = threadIdx.x;
    const int m0 = blockIdx.x * 64;
    const int tx = tid & 15, ty = tid >> 4;

    // A loader: one gathered row pointer per thread
    const int r = tid & 63;
    const int ha = tid >> 6;                      // 0..3
    {
        // nothing
    }
    const int m = m0 + r;
    const int b = m / Sdim, s = m - b * Sdim;
    const float* Ap = (s == 0) ? (g_init + (size_t)b * Edim)
                               : (emb + (size_t)sent[b * Tdim + (s - 1)] * Edim);
    // B loader
    const int rb = tid & 127;
    const int hb = tid >> 7;                      // 0..1
    const float* Bp = Wih0 + (size_t)rb * Edim;

    unsigned long long acc[8][2];
#pragma unroll
    for (int j = 0; j < 8; j++) { acc[j][0] = 0ull; acc[j][1] = 0ull; }

    for (int kc = 0; kc < 256; kc += 32) {
#pragma unroll
        for (int i = 0; i < 2; i++) {
            int seg = ha + i * 4;
            float4 v = *(const float4*)(Ap + kc + seg * 4);
            As[seg * 4 + 0][r] = v.x; As[seg * 4 + 1][r] = v.y;
            As[seg * 4 + 2][r] = v.z; As[seg * 4 + 3][r] = v.w;
        }
#pragma unroll
        for (int i = 0; i < 4; i++) {
            int seg = i * 2 + hb;
            float4 v = *(const float4*)(Bp + kc + seg * 4);
            Bs[seg * 4 + 0][rb] = v.x; Bs[seg * 4 + 1][rb] = v.y;
            Bs[seg * 4 + 2][rb] = v.z; Bs[seg * 4 + 3][rb] = v.w;
        }
        __syncthreads();
#pragma unroll 8
        for (int k = 0; k < 32; k++) {
            ulonglong2 a = *(const ulonglong2*)&As[k][ty * 4];
#pragma unroll
            for (int j = 0; j < 8; j++) {
                float bv = Bs[k][tx + j * 16];
                unsigned long long bd = pk2(bv, bv);
                acc[j][0] = fma2(a.x, bd, acc[j][0]);
                acc[j][1] = fma2(a.y, bd, acc[j][1]);
            }
        }
        __syncthreads();
    }
#pragma unroll
    for (int j = 0; j < 8; j++) {
        int n = tx + j * 16;
        float bias = bih0[n] + bhh0[n];
#pragma unroll
        for (int p = 0; p < 2; p++) {
            float2 v = up2(acc[j][p]);
            int mm = m0 + ty * 4 + p * 2;
            g_gx0[mm * G4 + n] = v.x + bias;
            g_gx0[(mm + 1) * G4 + n] = v.y + bias;
        }
    }
}

// ============================================================
// K3: fused 2-layer LSTM recurrence, 18 steps.
//     128 blocks x 128 threads; warp handles 2 batch rows; lane j = hidden unit.
//     W staged in smem gate-packed [k][j][4] -> one conflict-free LDS.128 per k.
// ============================================================
__global__ __launch_bounds__(128) void k_lstm(const float* __restrict__ Whh0,
                                              const float* __restrict__ Wih1,
                                              const float* __restrict__ Whh1,
                                              const float* __restrict__ bih1,
                                              const float* __restrict__ bhh1) {
    __shared__ __align__(16) float W0[32 * 128];   // [k][j][q]
    __shared__ __align__(16) float Wi1[32 * 128];
    __shared__ __align__(16) float Wh1[32 * 128];
    const int tid = threadIdx.x;

    for (int idx = tid; idx < 4096; idx += 128) {
        int k = idx >> 7, rem = idx & 127, j = rem >> 2, q = rem & 3;
        int src = (q * 32 + j) * 32 + k;
        W0[idx]  = Whh0[src];
        Wi1[idx] = Wih1[src];
        Wh1[idx] = Whh1[src];
    }
    __syncthreads();

    const int wid = tid >> 5, j = tid & 31;
    const int b0 = blockIdx.x * 8 + wid * 2;

    float b1q[4];
#pragma unroll
    for (int q = 0; q < 4; q++) b1q[q] = bih1[q * 32 + j] + bhh1[q * 32 + j];

    float hav[2] = {0.f, 0.f}, cav[2] = {0.f, 0.f};
    float hbv[2] = {0.f, 0.f}, cbv[2] = {0.f, 0.f};

    float pre[2][4];
#pragma unroll
    for (int rr = 0; rr < 2; rr++) {
        int m = (b0 + rr) * Sdim;
#pragma unroll
        for (int q = 0; q < 4; q++) pre[rr][q] = g_gx0[m * G4 + q * 32 + j];
    }

    for (int s = 0; s < Sdim; s++) {
        float gl[2][4];
#pragma unroll
        for (int rr = 0; rr < 2; rr++)
#pragma unroll
            for (int q = 0; q < 4; q++) gl[rr][q] = pre[rr][q];
        if (s < Sdim - 1) {
#pragma unroll
            for (int rr = 0; rr < 2; rr++) {
                int m = (b0 + rr) * Sdim + s + 1;
#pragma unroll
                for (int q = 0; q < 4; q++) pre[rr][q] = g_gx0[m * G4 + q * 32 + j];
            }
        }
        // ---- layer 0: g += W_hh0 @ h ----
#pragma unroll
        for (int k = 0; k < 32; k++) {
            float4 w = *(const float4*)&W0[k * 128 + j * 4];
            float h0 = __shfl_sync(0xffffffffu, hav[0], k);
            float h1 = __shfl_sync(0xffffffffu, hav[1], k);
            gl[0][0] += w.x * h0; gl[0][1] += w.y * h0;
            gl[0][2] += w.z * h0; gl[0][3] += w.w * h0;
            gl[1][0] += w.x * h1; gl[1][1] += w.y * h1;
            gl[1][2] += w.z * h1; gl[1][3] += w.w * h1;
        }
#pragma unroll
        for (int rr = 0; rr < 2; rr++) {
            float ci = sigf(gl[rr][0]), cf = sigf(gl[rr][1]);
            float cg = tanhf(gl[rr][2]), co = sigf(gl[rr][3]);
            cav[rr] = cf * cav[rr] + ci * cg;
            hav[rr] = co * tanhf(cav[rr]);
        }
        // ---- layer 1: g = b1 + W_ih1 @ h_l0 + W_hh1 @ h_l1_prev ----
        float G[2][4];
#pragma unroll
        for (int rr = 0; rr < 2; rr++)
#pragma unroll
            for (int q = 0; q < 4; q++) G[rr][q] = b1q[q];
#pragma unroll
        for (int k = 0; k < 32; k++) {
            float4 wi = *(const float4*)&Wi1[k * 128 + j * 4];
            float4 wh = *(const float4*)&Wh1[k * 128 + j * 4];
            float a0 = __shfl_sync(0xffffffffu, hav[0], k);
            float a1 = __shfl_sync(0xffffffffu, hav[1], k);
            float p0 = __shfl_sync(0xffffffffu, hbv[0], k);
            float p1 = __shfl_sync(0xffffffffu, hbv[1], k);
            G[0][0] += wi.x * a0 + wh.x * p0; G[0][1] += wi.y * a0 + wh.y * p0;
            G[0][2] += wi.z * a0 + wh.z * p0; G[0][3] += wi.w * a0 + wh.w * p0;
            G[1][0] += wi.x * a1 + wh.x * p1; G[1][1] += wi.y * a1 + wh.y * p1;
            G[1][2] += wi.z * a1 + wh.z * p1; G[1][3] += wi.w * a1 + wh.w * p1;
        }
#pragma unroll
        for (int rr = 0; rr < 2; rr++) {
            float ci = sigf(G[rr][0]), cf = sigf(G[rr][1]);
            float cg = tanhf(G[rr][2]), co = sigf(G[rr][3]);
            cbv[rr] = cf * cbv[rr] + ci * cg;
            hbv[rr] = co * tanhf(cbv[rr]);
            g_h2[((b0 + rr) * Sdim + s) * Hdim + j] = hbv[rr];
        }
    }
}

// ============================================================
// K4: out[m, v] = h2[m,:] . W_out[v,:] + b_out[v]
//     M=18432, N=14463, K=32 (single shot). 128x128 tile, f32x2 accumulators.
// ============================================================
__global__ __launch_bounds__(256) void k_out(const float* __restrict__ Wout,
                                             const float* __restrict__ bout,
                                             float* __restrict__ out) {
    __shared__ __align__(16) float Ah[32][128];   // [k][m]
    __shared__ __align__(16) float Bw[32][128];   // [k][n]
    const int tid = threadIdx.x;
    const int m0 = blockIdx.y * 128;
    const int n0 = blockIdx.x * 128;

    const int r = tid & 127;
    const int hseg = tid >> 7;                    // 0/1
    const float* Ap = g_h2 + (size_t)(m0 + r) * 32;
    const int nr = n0 + r;
    const bool nok = nr < Vdim;
    const float* Bp = Wout + (size_t)nr * 32;

#pragma unroll
    for (int i = 0; i < 4; i++) {
        int seg = i * 2 + hseg;
        float4 va = *(const float4*)(Ap + seg * 4);
        Ah[seg * 4 + 0][r] = va.x; Ah[seg * 4 + 1][r] = va.y;
        Ah[seg * 4 + 2][r] = va.z; Ah[seg * 4 + 3][r] = va.w;
        float4 vb = nok ? *(const float4*)(Bp + seg * 4) : make_float4(0.f, 0.f, 0.f, 0.f);
        Bw[seg * 4 + 0][r] = vb.x; Bw[seg * 4 + 1][r] = vb.y;
        Bw[seg * 4 + 2][r] = vb.z; Bw[seg * 4 + 3][r] = vb.w;
    }
    __syncthreads();

    const int tx = tid & 15, ty = tid >> 4;
    unsigned long long acc[8][4];
#pragma unroll
    for (int j = 0; j < 8; j++)
#pragma unroll
        for (int p = 0; p < 4; p++) acc[j][p] = 0ull;

#pragma unroll 4
    for (int k = 0; k < 32; k++) {
        ulonglong2 aA = *(const ulonglong2*)&Ah[k][ty * 8];
        ulonglong2 aB = *(const ulonglong2*)&Ah[k][ty * 8 + 4];
#pragma unroll
        for (int j = 0; j < 8; j++) {
            float bv = Bw[k][tx + j * 16];
            unsigned long long bd = pk2(bv, bv);
            acc[j][0] = fma2(aA.x, bd, acc[j][0]);
            acc[j][1] = fma2(aA.y, bd, acc[j][1]);
            acc[j][2] = fma2(aB.x, bd, acc[j][2]);
            acc[j][3] = fma2(aB.y, bd, acc[j][3]);
        }
    }

#pragma unroll
    for (int j = 0; j < 8; j++) {
        int n = n0 + tx + j * 16;
        if (n < Vdim) {
            float bias = bout[n];
#pragma unroll
            for (int p = 0; p < 4; p++) {
                float2 v = up2(acc[j][p]);
                size_t m = (size_t)(m0 + ty * 8 + p * 2);
                out[m * Vdim + n] = v.x + bias;
                out[(m + 1) * Vdim + n] = v.y + bias;
            }
        }
    }
}

// ============================================================
extern "C" void kernel_launch(void* const* d_in, const int* in_sizes, int n_in,
                              void* d_out, int out_size) {
    const float* graph = (const float*)d_in[0];
    const int*   sent  = (const int*)d_in[1];
    const float* Wg2e  = (const float*)d_in[2];
    const float* bg2e  = (const float*)d_in[3];
    const float* emb   = (const float*)d_in[4];
    const float* Wih0  = (const float*)d_in[5];
    const float* Whh0  = (const float*)d_in[6];
    const float* bih0  = (const float*)d_in[7];
    const float* bhh0  = (const float*)d_in[8];
    const float* Wih1  = (const float*)d_in[9];
    const float* Whh1  = (const float*)d_in[10];
    const float* bih1  = (const float*)d_in[11];
    const float* bhh1  = (const float*)d_in[12];
    const float* Wout  = (const float*)d_in[13];
    const float* bout  = (const float*)d_in[14];
    float* out = (float*)d_out;

    k_initbias<<<512, 512>>>(bg2e);
    k_proj<<<dim3(4, 16, 8), 256>>>(graph, Wg2e);
    k_gx<<<288, 256>>>(sent, emb, Wih0, bih0, bhh0);
    k_lstm<<<128, 128>>>(Whh0, Wih1, Whh1, bih1, bhh1);
    k_out<<<dim3(113, 144), 256>>>(Wout, bout, out);
}